// round 8
// baseline (speedup 1.0000x reference)
#include <cuda_runtime.h>
#include <cstdint>

// Problem shape (fixed by dataset): B=2, S=2048, A=16, H=1024, NH=16, HD=64
#define BB 2
#define SS 2048
#define AA 16
#define HH 1024
#define NH 16
#define HD 64

// ---- scratch (device globals; no allocation allowed) ----
__device__ __align__(16) float g_q[BB * HH];           // q[b, o]
__device__ __align__(16) float g_v[BB * NH * HH];      // folded key weights v[b, h, i]
__device__ __align__(16) float g_e[BB * NH * SS];      // e[b,h,k] = masked exp(score)
__device__ __align__(16) float g_z[BB * NH];           // per-(b,h) sum of e

// ---- mask dtype detection (sentence_mask[0][0..3] always true since len >= S/2) ----
__device__ __forceinline__ int detect_mode(const void* sm) {
    unsigned int w0 = *(const unsigned int*)sm;
    if (w0 == 0x01010101u) return 1;   // 1-byte bool
    if (w0 == 0x3F800000u) return 2;   // float32
    if (w0 == 0x3F803F80u) return 3;   // bf16
    return 0;                          // int32
}
__device__ __forceinline__ bool mask_at(const void* p, int idx, int mode) {
    switch (mode) {
        case 1:  return ((const unsigned char*)p)[idx] != 0;
        case 2:  return ((const float*)p)[idx] != 0.0f;
        case 3:  return ((const unsigned short*)p)[idx] != 0;
        default: return ((const int*)p)[idx] != 0;
    }
}

// ==== K1: agg (masked mean) + q rows.  grid (BB, 8) = 16 blocks, block 512. ====
__global__ void __launch_bounds__(512) k_aggq(const float* __restrict__ h2,
                                              const void* __restrict__ am,
                                              const void* __restrict__ sm,
                                              const float* __restrict__ Wq) {
    int b = blockIdx.x;
    int mode = detect_mode(sm);
    int t = threadIdx.x, warp = t >> 5, lane = t & 31;
    __shared__ float agg[HH];

    float cnt = 0.f;
#pragma unroll
    for (int a = 0; a < AA; a++) cnt += mask_at(am, b * AA + a, mode) ? 1.f : 0.f;
    float inv = 1.f / fmaxf(cnt, 1.f);
#pragma unroll
    for (int p = 0; p < 2; p++) {
        int i = t + p * 512;
        float s = 0.f;
#pragma unroll
        for (int a = 0; a < AA; a++)
            if (mask_at(am, b * AA + a, mode)) s += h2[(b * AA + a) * HH + i];
        agg[i] = s * inv;
    }
    __syncthreads();

    const float4* ag4 = (const float4*)agg;
#pragma unroll
    for (int r = 0; r < 8; r++) {
        int o = blockIdx.y * 128 + warp * 8 + r;
        const float4* wrow = (const float4*)(Wq + (size_t)o * HH);
        float acc = 0.f;
#pragma unroll
        for (int j = 0; j < HH / 128; j++) {
            float4 wv = wrow[lane + j * 32];
            float4 av = ag4[lane + j * 32];
            acc += wv.x * av.x + wv.y * av.y + wv.z * av.z + wv.w * av.w;
        }
#pragma unroll
        for (int off = 16; off; off >>= 1) acc += __shfl_xor_sync(0xffffffffu, acc, off);
        if (lane == 0) g_q[b * HH + o] = acc;
    }
}

// ==== K2: fold q into Wk: v[b,h,i] = sum_o q[b,h*64+o] * Wk[h*64+o, i]. ====
// grid (BB*NH, 4) = 128 blocks, block 256. Also zeroes g_z for K3's atomics.
__global__ void __launch_bounds__(256) k_fold(const float* __restrict__ Wk) {
    int b = blockIdx.x >> 4;
    int h = blockIdx.x & 15;
    int i = blockIdx.y * 256 + threadIdx.x;
    if (blockIdx.x == 0 && blockIdx.y == 0 && threadIdx.x < BB * NH)
        g_z[threadIdx.x] = 0.f;
    __shared__ float qs[HD];
    if (threadIdx.x < HD) qs[threadIdx.x] = g_q[b * HH + h * HD + threadIdx.x];
    __syncthreads();
    float acc = 0.f;
#pragma unroll 8
    for (int o = 0; o < HD; o++)
        acc += qs[o] * Wk[(size_t)(h * HD + o) * HH + i];
    g_v[(size_t)(b * NH + h) * HH + i] = acc;
}

// ==== K3: e[b,h,k] = mask(k) ? exp(0.125 * dot(v[b,h,:], h1[b,k,:])) : 0 ====
// Also atomically accumulates z[b,h] = sum_k e.  (No max-subtraction needed:
// |score| is bounded by construction; exp cannot overflow.)
// 8 heads per block (32KB smem), 8 warps x 4 k; grid (BB, 64, 2) = 256 blocks.
__global__ void __launch_bounds__(256, 2) k_scores(const float* __restrict__ h1,
                                                   const void* __restrict__ sm) {
    __shared__ float4 vs4[8 * HH / 4];   // 8 heads x 1024 floats = 32 KB
    int b = blockIdx.x;
    int hh = blockIdx.z;                 // head half: heads [hh*8, hh*8+8)
    int t = threadIdx.x;

    const float4* vb = (const float4*)(g_v + (size_t)(b * NH + hh * 8) * HH);
#pragma unroll
    for (int j = 0; j < 8; j++) vs4[t + j * 256] = vb[t + j * 256];
    __syncthreads();

    int warp = t >> 5, lane = t & 31;
    int k0 = blockIdx.y * 32 + warp * 4;

    const float4* r0 = (const float4*)(h1 + (size_t)(b * SS + k0 + 0) * HH);
    const float4* r1 = (const float4*)(h1 + (size_t)(b * SS + k0 + 1) * HH);
    const float4* r2 = (const float4*)(h1 + (size_t)(b * SS + k0 + 2) * HH);
    const float4* r3 = (const float4*)(h1 + (size_t)(b * SS + k0 + 3) * HH);

    float acc[8][4];
#pragma unroll
    for (int h = 0; h < 8; h++)
#pragma unroll
        for (int j = 0; j < 4; j++) acc[h][j] = 0.f;

#pragma unroll 2
    for (int m = 0; m < HH / 128; m++) {
        int idx = lane + m * 32;
        float4 x0 = r0[idx], x1 = r1[idx], x2 = r2[idx], x3 = r3[idx];
#pragma unroll
        for (int h = 0; h < 8; h++) {
            float4 v = vs4[h * (HH / 4) + idx];
            acc[h][0] += v.x * x0.x + v.y * x0.y + v.z * x0.z + v.w * x0.w;
            acc[h][1] += v.x * x1.x + v.y * x1.y + v.z * x1.z + v.w * x1.w;
            acc[h][2] += v.x * x2.x + v.y * x2.y + v.z * x2.z + v.w * x2.w;
            acc[h][3] += v.x * x3.x + v.y * x3.y + v.z * x3.z + v.w * x3.w;
        }
    }
#pragma unroll
    for (int h = 0; h < 8; h++)
#pragma unroll
        for (int j = 0; j < 4; j++) {
            float s = acc[h][j];
#pragma unroll
            for (int off = 16; off; off >>= 1) s += __shfl_xor_sync(0xffffffffu, s, off);
            acc[h][j] = s;
        }
    // 32 lanes = 8 heads x 4 k: apply mask + exp, store e, accumulate z.
    {
        int mode = detect_mode(sm);
        int h = lane & 7, j = lane >> 3;
        int k = k0 + j;
        float e = 0.f;
        if (mask_at(sm, b * SS + k, mode)) e = __expf(acc[h][j] * 0.125f);
        g_e[(size_t)(b * NH + hh * 8 + h) * SS + k] = e;
        atomicAdd(&g_z[b * NH + hh * 8 + h], e);
    }
}

// ==== K4: fused weights + TMA broadcast.  grid (BB, 32) = 64 blocks, 256 thr. ====
// Each block computes the full w[b,:] row into smem (redundant across the 32
// row-chunk blocks: 64 x 128KB = 8MB of L2 e-reads, ~0.7us aggregate), then
// threads 0-63 each fire one 8KB cp.async.bulk store for one of the block's
// 64 output rows. 64 SMs of TMA issue saturate the ~6.3KB/cyc LTS cap.
__global__ void __launch_bounds__(256) k_wbcast(float* __restrict__ out) {
    __shared__ __align__(16) float wsh[SS];
    __shared__ float ziv[NH];
    int b = blockIdx.x;
    int t = threadIdx.x;

    if (t < NH) ziv[t] = 1.f / (g_z[b * NH + t] * (float)NH);
    __syncthreads();

    // w for 8 consecutive columns per thread (2 float4 per head slice)
    {
        const float4* e4 = (const float4*)g_e;
        float4 w0 = {0.f, 0.f, 0.f, 0.f}, w1 = {0.f, 0.f, 0.f, 0.f};
#pragma unroll
        for (int h = 0; h < NH; h++) {
            float zi = ziv[h];
            size_t base = (size_t)(b * NH + h) * (SS / 4) + t * 2;
            float4 e0 = e4[base], e1 = e4[base + 1];
            w0.x += e0.x * zi; w0.y += e0.y * zi; w0.z += e0.z * zi; w0.w += e0.w * zi;
            w1.x += e1.x * zi; w1.y += e1.y * zi; w1.z += e1.z * zi; w1.w += e1.w * zi;
        }
        ((float4*)wsh)[t * 2] = w0;
        ((float4*)wsh)[t * 2 + 1] = w1;
    }
    __syncthreads();
    asm volatile("fence.proxy.async.shared::cta;" ::: "memory");

    unsigned int saddr;
    asm("{ .reg .u64 tmp; cvta.to.shared.u64 tmp, %1; cvt.u32.u64 %0, tmp; }"
        : "=r"(saddr) : "l"(wsh));

    int r0 = blockIdx.y * 64;
    if (t < 64) {
        float* dst = out + (size_t)(b * SS + r0 + t) * SS;
        unsigned int nbytes = SS * 4;
        asm volatile("cp.async.bulk.global.shared::cta.bulk_group [%0], [%1], %2;"
                     :: "l"(dst), "r"(saddr), "r"(nbytes) : "memory");
        asm volatile("cp.async.bulk.commit_group;" ::: "memory");
        asm volatile("cp.async.bulk.wait_group 0;" ::: "memory");
    }
}

extern "C" void kernel_launch(void* const* d_in, const int* in_sizes, int n_in,
                              void* d_out, int out_size) {
    const float* h1 = (const float*)d_in[0];   // [B,S,H]
    const float* h2 = (const float*)d_in[1];   // [B,A,H]
    const void*  sm = d_in[2];                 // [B,S]
    const void*  am = d_in[3];                 // [B,A]
    const float* Wq = (const float*)d_in[4];   // [H,H]
    const float* Wk = (const float*)d_in[5];   // [H,H]
    float* out = (float*)d_out;                // [B,S,S]

    k_aggq<<<dim3(BB, 8), 512>>>(h2, am, sm, Wq);
    k_fold<<<dim3(BB * NH, 4), 256>>>(Wk);
    k_scores<<<dim3(BB, 64, 2), 256>>>(h1, sm);
    k_wbcast<<<dim3(BB, 32), 256>>>(out);
}

// round 9
// speedup vs baseline: 1.0602x; 1.0602x over previous
#include <cuda_runtime.h>
#include <cstdint>

// Problem shape (fixed by dataset): B=2, S=2048, A=16, H=1024, NH=16, HD=64
#define BB 2
#define SS 2048
#define AA 16
#define HH 1024
#define NH 16
#define HD 64

// ---- scratch (device globals; no allocation allowed) ----
__device__ __align__(16) float g_v[BB * NH * HH];      // folded key weights v[b, h, i]
__device__ __align__(16) float g_e[BB * NH * SS];      // e[b,h,k] = masked exp(score)
__device__ __align__(16) float g_z[BB * NH];           // per-(b,h) sum of e

// ---- mask dtype detection (sentence_mask[0][0..3] always true since len >= S/2) ----
__device__ __forceinline__ int detect_mode(const void* sm) {
    unsigned int w0 = *(const unsigned int*)sm;
    if (w0 == 0x01010101u) return 1;   // 1-byte bool
    if (w0 == 0x3F800000u) return 2;   // float32
    if (w0 == 0x3F803F80u) return 3;   // bf16
    return 0;                          // int32
}
__device__ __forceinline__ bool mask_at(const void* p, int idx, int mode) {
    switch (mode) {
        case 1:  return ((const unsigned char*)p)[idx] != 0;
        case 2:  return ((const float*)p)[idx] != 0.0f;
        case 3:  return ((const unsigned short*)p)[idx] != 0;
        default: return ((const int*)p)[idx] != 0;
    }
}

// ==== K1: fused agg + q(head) + fold -> v[b,h,:].  grid BB*NH = 32 blocks, 256 thr. ====
// Each (b,h) block: masked-mean agg (64KB h2, redundant x16 = 2MB total),
// q rows for its head (64 x 1024 Wq = 256KB), fold into v (256KB Wk).
// Also zeroes its g_z slot for K2's atomics.
__global__ void __launch_bounds__(256) k_qv(const float* __restrict__ h2,
                                            const void* __restrict__ am,
                                            const void* __restrict__ sm,
                                            const float* __restrict__ Wq,
                                            const float* __restrict__ Wk) {
    int b = blockIdx.x >> 4;
    int h = blockIdx.x & 15;
    int mode = detect_mode(sm);
    int t = threadIdx.x, warp = t >> 5, lane = t & 31;

    __shared__ float agg[HH];
    __shared__ float qs[HD];

    if (t == 0) g_z[blockIdx.x] = 0.f;

    // (a) masked mean of h2 over aspects
    float cnt = 0.f;
#pragma unroll
    for (int a = 0; a < AA; a++) cnt += mask_at(am, b * AA + a, mode) ? 1.f : 0.f;
    float inv = 1.f / fmaxf(cnt, 1.f);
#pragma unroll
    for (int p = 0; p < 4; p++) {
        int i = t + p * 256;
        float s = 0.f;
#pragma unroll
        for (int a = 0; a < AA; a++)
            if (mask_at(am, b * AA + a, mode)) s += h2[(b * AA + a) * HH + i];
        agg[i] = s * inv;
    }
    __syncthreads();

    // (b) q rows of this head: 8 warps x 8 rows
    const float4* ag4 = (const float4*)agg;
#pragma unroll
    for (int r = 0; r < 8; r++) {
        int o = h * HD + warp * 8 + r;
        const float4* wrow = (const float4*)(Wq + (size_t)o * HH);
        float acc = 0.f;
#pragma unroll
        for (int j = 0; j < HH / 128; j++) {
            float4 wv = wrow[lane + j * 32];
            float4 av = ag4[lane + j * 32];
            acc += wv.x * av.x + wv.y * av.y + wv.z * av.z + wv.w * av.w;
        }
#pragma unroll
        for (int off = 16; off; off >>= 1) acc += __shfl_xor_sync(0xffffffffu, acc, off);
        if (lane == 0) qs[warp * 8 + r] = acc;
    }
    __syncthreads();

    // (c) fold: v[b,h,i] = sum_o qs[o] * Wk[h*64+o, i]; thread handles 4 i's
    const float* wkbase = Wk + (size_t)(h * HD) * HH;
#pragma unroll
    for (int p = 0; p < 4; p++) {
        int i = t + p * 256;
        float acc = 0.f;
#pragma unroll 8
        for (int o = 0; o < HD; o++)
            acc += qs[o] * wkbase[(size_t)o * HH + i];
        g_v[(size_t)(b * NH + h) * HH + i] = acc;
    }
}

// ==== K2: e[b,h,k] = mask(k) ? exp(0.125 * dot(v[b,h,:], h1[b,k,:])) : 0 ====
// Also atomically accumulates z[b,h] = sum_k e.  (No max-subtraction needed:
// |score| is bounded by construction; exp cannot overflow.)
// 8 heads per block (32KB smem), 8 warps x 4 k; grid (BB, 64, 2) = 256 blocks.
__global__ void __launch_bounds__(256, 2) k_scores(const float* __restrict__ h1,
                                                   const void* __restrict__ sm) {
    __shared__ float4 vs4[8 * HH / 4];   // 8 heads x 1024 floats = 32 KB
    int b = blockIdx.x;
    int hh = blockIdx.z;                 // head half: heads [hh*8, hh*8+8)
    int t = threadIdx.x;

    const float4* vb = (const float4*)(g_v + (size_t)(b * NH + hh * 8) * HH);
#pragma unroll
    for (int j = 0; j < 8; j++) vs4[t + j * 256] = vb[t + j * 256];
    __syncthreads();

    int warp = t >> 5, lane = t & 31;
    int k0 = blockIdx.y * 32 + warp * 4;

    const float4* r0 = (const float4*)(h1 + (size_t)(b * SS + k0 + 0) * HH);
    const float4* r1 = (const float4*)(h1 + (size_t)(b * SS + k0 + 1) * HH);
    const float4* r2 = (const float4*)(h1 + (size_t)(b * SS + k0 + 2) * HH);
    const float4* r3 = (const float4*)(h1 + (size_t)(b * SS + k0 + 3) * HH);

    float acc[8][4];
#pragma unroll
    for (int h = 0; h < 8; h++)
#pragma unroll
        for (int j = 0; j < 4; j++) acc[h][j] = 0.f;

#pragma unroll 2
    for (int m = 0; m < HH / 128; m++) {
        int idx = lane + m * 32;
        float4 x0 = r0[idx], x1 = r1[idx], x2 = r2[idx], x3 = r3[idx];
#pragma unroll
        for (int h = 0; h < 8; h++) {
            float4 v = vs4[h * (HH / 4) + idx];
            acc[h][0] += v.x * x0.x + v.y * x0.y + v.z * x0.z + v.w * x0.w;
            acc[h][1] += v.x * x1.x + v.y * x1.y + v.z * x1.z + v.w * x1.w;
            acc[h][2] += v.x * x2.x + v.y * x2.y + v.z * x2.z + v.w * x2.w;
            acc[h][3] += v.x * x3.x + v.y * x3.y + v.z * x3.z + v.w * x3.w;
        }
    }
#pragma unroll
    for (int h = 0; h < 8; h++)
#pragma unroll
        for (int j = 0; j < 4; j++) {
            float s = acc[h][j];
#pragma unroll
            for (int off = 16; off; off >>= 1) s += __shfl_xor_sync(0xffffffffu, s, off);
            acc[h][j] = s;
        }
    // 32 lanes = 8 heads x 4 k: apply mask + exp, store e, accumulate z.
    {
        int mode = detect_mode(sm);
        int h = lane & 7, j = lane >> 3;
        int k = k0 + j;
        float e = 0.f;
        if (mask_at(sm, b * SS + k, mode)) e = __expf(acc[h][j] * 0.125f);
        g_e[(size_t)(b * NH + hh * 8 + h) * SS + k] = e;
        atomicAdd(&g_z[b * NH + hh * 8 + h], e);
    }
}

// ==== K3: fused weights + broadcast.  grid (BB, 8 colchunks, 32 rowchunks) = 512 blocks. ====
// Tile = 256 cols x 64 rows. All 256 threads compute one w column each
// (16 coalesced e loads), then each warp writes 8 rows x 256 cols with
// 16 independent streaming STG.128 per thread (__stcs: L2-direct hint).
__global__ void __launch_bounds__(256) k_wbcast(float* __restrict__ out) {
    __shared__ __align__(16) float wsh[256];
    __shared__ float ziv[NH];
    int b = blockIdx.x;
    int c0 = blockIdx.y * 256;
    int r0 = blockIdx.z * 64;
    int t = threadIdx.x;

    if (t < NH) ziv[t] = 1.f / (g_z[b * NH + t] * (float)NH);
    __syncthreads();

    {
        int k = c0 + t;
        float wv = 0.f;
#pragma unroll
        for (int h = 0; h < NH; h++)
            wv += g_e[(size_t)(b * NH + h) * SS + k] * ziv[h];
        wsh[t] = wv;
    }
    __syncthreads();

    int warp = t >> 5, lane = t & 31;
    float4 v0 = ((const float4*)wsh)[lane];
    float4 v1 = ((const float4*)wsh)[lane + 32];
    int rowbase = r0 + warp * 8;
#pragma unroll
    for (int j = 0; j < 8; j++) {
        float4* dst = (float4*)(out + (size_t)(b * SS + rowbase + j) * SS + c0);
        __stcs(dst + lane, v0);
        __stcs(dst + lane + 32, v1);
    }
}

extern "C" void kernel_launch(void* const* d_in, const int* in_sizes, int n_in,
                              void* d_out, int out_size) {
    const float* h1 = (const float*)d_in[0];   // [B,S,H]
    const float* h2 = (const float*)d_in[1];   // [B,A,H]
    const void*  sm = d_in[2];                 // [B,S]
    const void*  am = d_in[3];                 // [B,A]
    const float* Wq = (const float*)d_in[4];   // [H,H]
    const float* Wk = (const float*)d_in[5];   // [H,H]
    float* out = (float*)d_out;                // [B,S,S]

    k_qv<<<BB * NH, 256>>>(h2, am, sm, Wq, Wk);
    k_scores<<<dim3(BB, 64, 2), 256>>>(h1, sm);
    k_wbcast<<<dim3(BB, 8, 32), 256>>>(out);
}

// round 10
// speedup vs baseline: 1.2538x; 1.1827x over previous
#include <cuda_runtime.h>
#include <cstdint>

// Problem shape (fixed by dataset): B=2, S=2048, A=16, H=1024, NH=16, HD=64
#define BB 2
#define SS 2048
#define AA 16
#define HH 1024
#define NH 16
#define HD 64
#define NBLK 256

// ---- scratch (device globals; no allocation allowed) ----
__device__ __align__(16) float g_q[BB * HH];           // q[b, o]
__device__ __align__(16) float g_v[BB * NH * HH];      // folded key weights v[b, h, i]
__device__ __align__(16) float g_e[BB * NH * SS];      // e[b,h,k] = masked exp(score)
__device__ __align__(16) float g_z[BB * NH];           // per-(b,h) sum of e
__device__ unsigned int g_bar[4];                      // monotonic grid-barrier counters

// ---- mask dtype detection (sentence_mask[0][0..3] always true since len >= S/2) ----
__device__ __forceinline__ int detect_mode(const void* sm) {
    unsigned int w0 = *(const unsigned int*)sm;
    if (w0 == 0x01010101u) return 1;   // 1-byte bool
    if (w0 == 0x3F800000u) return 2;   // float32
    if (w0 == 0x3F803F80u) return 3;   // bf16
    return 0;                          // int32
}
__device__ __forceinline__ bool mask_at(const void* p, int idx, int mode) {
    switch (mode) {
        case 1:  return ((const unsigned char*)p)[idx] != 0;
        case 2:  return ((const float*)p)[idx] != 0.0f;
        case 3:  return ((const unsigned short*)p)[idx] != 0;
        default: return ((const int*)p)[idx] != 0;
    }
}

// Grid barrier: monotonic ticket counter, no reset needed across graph replays.
// All NBLK blocks are guaranteed co-resident (see launch_bounds + grid sizing).
__device__ __forceinline__ void gbar(unsigned int* ctr) {
    __syncthreads();
    if (threadIdx.x == 0) {
        __threadfence();
        unsigned int ticket = atomicAdd(ctr, 1u);
        unsigned int target = (ticket / NBLK + 1u) * NBLK;
        while (atomicAdd(ctr, 0u) < target) { __nanosleep(64); }
        __threadfence();
    }
    __syncthreads();
}

__global__ void __launch_bounds__(256, 2) k_fused(
    const float* __restrict__ h1, const float* __restrict__ h2,
    const void* __restrict__ sm, const void* __restrict__ am,
    const float* __restrict__ Wq, const float* __restrict__ Wk,
    float* __restrict__ out)
{
    __shared__ __align__(16) float sh[8 * HH];   // 32 KB, reused per phase
    __shared__ float shq[HD];
    __shared__ float ziv[NH];

    int bid = blockIdx.x;
    int t = threadIdx.x, warp = t >> 5, lane = t & 31;
    int mode = detect_mode(sm);

    // ======== Phase 1: masked-mean agg + q rows (blocks 0..63) ========
    // block j: b = j>>5, q-rows [ (j&31)*32, +32 ).  agg recomputed per block (64KB h2).
    if (bid < 64) {
        int b = bid >> 5;
        int og = (bid & 31) * 32;
        if (bid == 0 && t < BB * NH) g_z[t] = 0.f;

        float cnt = 0.f;
#pragma unroll
        for (int a = 0; a < AA; a++) cnt += mask_at(am, b * AA + a, mode) ? 1.f : 0.f;
        float inv = 1.f / fmaxf(cnt, 1.f);
#pragma unroll
        for (int p = 0; p < 4; p++) {
            int i = t + p * 256;
            float s = 0.f;
#pragma unroll
            for (int a = 0; a < AA; a++)
                if (mask_at(am, b * AA + a, mode)) s += h2[(b * AA + a) * HH + i];
            sh[i] = s * inv;
        }
        __syncthreads();

        const float4* ag4 = (const float4*)sh;
#pragma unroll
        for (int r = 0; r < 4; r++) {
            int o = og + warp * 4 + r;
            const float4* wrow = (const float4*)(Wq + (size_t)o * HH);
            float acc = 0.f;
#pragma unroll
            for (int j = 0; j < 8; j++) {
                float4 wv = wrow[lane + j * 32];
                float4 av = ag4[lane + j * 32];
                acc += wv.x * av.x + wv.y * av.y + wv.z * av.z + wv.w * av.w;
            }
#pragma unroll
            for (int off = 16; off; off >>= 1) acc += __shfl_xor_sync(0xffffffffu, acc, off);
            if (lane == 0) g_q[b * HH + o] = acc;
        }
    }
    gbar(&g_bar[0]);

    // ======== Phase 2: fold q into Wk -> v[b,h,:] (blocks 0..127) ========
    // block j: b = j>>6, h = (j>>2)&15, quarter = j&3 (256 columns).
    if (bid < 128) {
        int b = bid >> 6, h = (bid >> 2) & 15, qtr = bid & 3;
        if (t < HD) shq[t] = g_q[b * HH + h * HD + t];
        __syncthreads();
        int i = qtr * 256 + t;
        const float* wkb = Wk + (size_t)(h * HD) * HH;
        float acc = 0.f;
#pragma unroll 8
        for (int o = 0; o < HD; o++)
            acc += shq[o] * wkb[(size_t)o * HH + i];
        g_v[(size_t)(b * NH + h) * HH + i] = acc;
        __syncthreads();
    }
    gbar(&g_bar[1]);

    // ======== Phase 3: e = mask ? exp(0.125 * v.h1) : 0 ; atomic z (all blocks) ========
    // block: b = bid>>7; kc = (bid&127)>>1 -> 32 k's; hh = bid&1 -> 8 heads (32KB smem).
    {
        int b = bid >> 7, rem = bid & 127, kc = rem >> 1, hh = rem & 1;
        float4* vs4 = (float4*)sh;
        const float4* vb = (const float4*)(g_v + (size_t)(b * NH + hh * 8) * HH);
#pragma unroll
        for (int j = 0; j < 8; j++) vs4[t + j * 256] = vb[t + j * 256];
        __syncthreads();

        int k0 = kc * 32 + warp * 4;
        const float4* r0 = (const float4*)(h1 + (size_t)(b * SS + k0 + 0) * HH);
        const float4* r1 = (const float4*)(h1 + (size_t)(b * SS + k0 + 1) * HH);
        const float4* r2 = (const float4*)(h1 + (size_t)(b * SS + k0 + 2) * HH);
        const float4* r3 = (const float4*)(h1 + (size_t)(b * SS + k0 + 3) * HH);

        float acc[8][4];
#pragma unroll
        for (int h = 0; h < 8; h++)
#pragma unroll
            for (int j = 0; j < 4; j++) acc[h][j] = 0.f;

#pragma unroll 2
        for (int m = 0; m < HH / 128; m++) {
            int idx = lane + m * 32;
            float4 x0 = r0[idx], x1 = r1[idx], x2 = r2[idx], x3 = r3[idx];
#pragma unroll
            for (int h = 0; h < 8; h++) {
                float4 v = vs4[h * (HH / 4) + idx];
                acc[h][0] += v.x * x0.x + v.y * x0.y + v.z * x0.z + v.w * x0.w;
                acc[h][1] += v.x * x1.x + v.y * x1.y + v.z * x1.z + v.w * x1.w;
                acc[h][2] += v.x * x2.x + v.y * x2.y + v.z * x2.z + v.w * x2.w;
                acc[h][3] += v.x * x3.x + v.y * x3.y + v.z * x3.z + v.w * x3.w;
            }
        }
#pragma unroll
        for (int h = 0; h < 8; h++)
#pragma unroll
            for (int j = 0; j < 4; j++) {
                float s = acc[h][j];
#pragma unroll
                for (int off = 16; off; off >>= 1) s += __shfl_xor_sync(0xffffffffu, s, off);
                acc[h][j] = s;
            }
        {
            int h = lane & 7, j = lane >> 3;
            int k = k0 + j;
            float e = 0.f;
            if (mask_at(sm, b * SS + k, mode)) e = __expf(acc[h][j] * 0.125f);
            g_e[(size_t)(b * NH + hh * 8 + h) * SS + k] = e;
            atomicAdd(&g_z[b * NH + hh * 8 + h], e);
        }
        __syncthreads();
    }
    gbar(&g_bar[2]);

    // ======== Phase 4: w[b,:] (redundant per block) + streaming broadcast ========
    // block: b = bid>>7; rows [ (bid&127)*16, +16 ).  Each block computes the full
    // 2048-col weight row into smem, then each warp writes 2 rows via __stcs.
    {
        int b = bid >> 7, rg = bid & 127, r0 = rg * 16;
        if (t < NH) ziv[t] = 1.f / (g_z[b * NH + t] * (float)NH);
        __syncthreads();

        const float4* e4 = (const float4*)g_e;
        float4 w0 = {0.f, 0.f, 0.f, 0.f}, w1 = {0.f, 0.f, 0.f, 0.f};
#pragma unroll
        for (int h = 0; h < NH; h++) {
            float zi = ziv[h];
            size_t base = (size_t)(b * NH + h) * (SS / 4);
            float4 e0 = e4[base + t];
            float4 e1 = e4[base + t + 256];
            w0.x += e0.x * zi; w0.y += e0.y * zi; w0.z += e0.z * zi; w0.w += e0.w * zi;
            w1.x += e1.x * zi; w1.y += e1.y * zi; w1.z += e1.z * zi; w1.w += e1.w * zi;
        }
        ((float4*)sh)[t] = w0;
        ((float4*)sh)[t + 256] = w1;
        __syncthreads();

        const float4* s4 = (const float4*)sh;
        size_t rowA = (size_t)(b * SS + r0 + warp * 2) * (SS / 4);
        size_t rowB = rowA + (SS / 4);
        float4* o4 = (float4*)out;
#pragma unroll 4
        for (int j = 0; j < 16; j++) {
            float4 v = s4[lane + j * 32];
            __stcs(o4 + rowA + lane + j * 32, v);
            __stcs(o4 + rowB + lane + j * 32, v);
        }
    }
}

extern "C" void kernel_launch(void* const* d_in, const int* in_sizes, int n_in,
                              void* d_out, int out_size) {
    const float* h1 = (const float*)d_in[0];   // [B,S,H]
    const float* h2 = (const float*)d_in[1];   // [B,A,H]
    const void*  sm = d_in[2];                 // [B,S]
    const void*  am = d_in[3];                 // [B,A]
    const float* Wq = (const float*)d_in[4];   // [H,H]
    const float* Wk = (const float*)d_in[5];   // [H,H]
    float* out = (float*)d_out;                // [B,S,S]

    k_fused<<<NBLK, 256>>>(h1, h2, sm, am, Wq, Wk, out);
}

// round 11
// speedup vs baseline: 1.2710x; 1.0136x over previous
#include <cuda_runtime.h>
#include <cstdint>

// Problem shape (fixed by dataset): B=2, S=2048, A=16, H=1024, NH=16, HD=64
#define BB 2
#define SS 2048
#define AA 16
#define HH 1024
#define NH 16
#define HD 64
#define NBLK 256

// ---- scratch (device globals; no allocation allowed) ----
__device__ __align__(16) float g_q[BB * HH];           // q[b, o]
__device__ __align__(16) float g_v[BB * NH * HH];      // folded key weights v[b, h, i]
__device__ __align__(16) float g_e[BB * NH * SS];      // e[b,h,k] = masked exp(score)
__device__ __align__(16) float g_z[BB * NH];           // per-(b,h) sum of e
__device__ unsigned int g_bar[4];                      // monotonic grid-barrier counters

// ---- mask dtype detection (sentence_mask[0][0..3] always true since len >= S/2) ----
__device__ __forceinline__ int detect_mode(const void* sm) {
    unsigned int w0 = *(const unsigned int*)sm;
    if (w0 == 0x01010101u) return 1;   // 1-byte bool
    if (w0 == 0x3F800000u) return 2;   // float32
    if (w0 == 0x3F803F80u) return 3;   // bf16
    return 0;                          // int32
}
__device__ __forceinline__ bool mask_at(const void* p, int idx, int mode) {
    switch (mode) {
        case 1:  return ((const unsigned char*)p)[idx] != 0;
        case 2:  return ((const float*)p)[idx] != 0.0f;
        case 3:  return ((const unsigned short*)p)[idx] != 0;
        default: return ((const int*)p)[idx] != 0;
    }
}

// Grid barrier: monotonic ticket counter, no reset needed across graph replays.
// All NBLK blocks are co-resident (148 SMs x 2 blocks >= 256), so spinning is safe.
__device__ __forceinline__ void gbar(unsigned int* ctr) {
    __syncthreads();
    if (threadIdx.x == 0) {
        __threadfence();
        unsigned int ticket = atomicAdd(ctr, 1u);
        unsigned int target = (ticket / NBLK + 1u) * NBLK;
        while (atomicAdd(ctr, 0u) < target) { __nanosleep(64); }
        __threadfence();
    }
    __syncthreads();
}

__global__ void __launch_bounds__(256, 2) k_fused(
    const float* __restrict__ h1, const float* __restrict__ h2,
    const void* __restrict__ sm, const void* __restrict__ am,
    const float* __restrict__ Wq, const float* __restrict__ Wk,
    float* __restrict__ out)
{
    __shared__ __align__(16) float sh[8 * HH];   // 32 KB, reused per phase
    __shared__ float shq[HD];
    __shared__ float ziv[NH];

    int bid = blockIdx.x;
    int t = threadIdx.x, warp = t >> 5, lane = t & 31;
    int mode = detect_mode(sm);

    // ======== Phase 1: masked-mean agg + q rows (ALL 256 blocks) ========
    // block: b = bid>>7, rows [ (bid&127)*8, +8 ), one row per warp.
    // agg recomputed per block (64KB h2 L2-reads x256 = 16MB aggregate, parallel).
    {
        int b = bid >> 7;
        int og = (bid & 127) * 8;
        if (bid == 0 && t < BB * NH) g_z[t] = 0.f;

        float cnt = 0.f;
#pragma unroll
        for (int a = 0; a < AA; a++) cnt += mask_at(am, b * AA + a, mode) ? 1.f : 0.f;
        float inv = 1.f / fmaxf(cnt, 1.f);
#pragma unroll
        for (int p = 0; p < 4; p++) {
            int i = t + p * 256;
            float s = 0.f;
#pragma unroll
            for (int a = 0; a < AA; a++)
                if (mask_at(am, b * AA + a, mode)) s += h2[(b * AA + a) * HH + i];
            sh[i] = s * inv;
        }
        __syncthreads();

        const float4* ag4 = (const float4*)sh;
        int o = og + warp;
        const float4* wrow = (const float4*)(Wq + (size_t)o * HH);
        float acc = 0.f;
#pragma unroll
        for (int j = 0; j < 8; j++) {
            float4 wv = wrow[lane + j * 32];
            float4 av = ag4[lane + j * 32];
            acc += wv.x * av.x + wv.y * av.y + wv.z * av.z + wv.w * av.w;
        }
#pragma unroll
        for (int off = 16; off; off >>= 1) acc += __shfl_xor_sync(0xffffffffu, acc, off);
        if (lane == 0) g_q[b * HH + o] = acc;
        __syncthreads();
    }
    gbar(&g_bar[0]);

    // ======== Phase 2: fold q into Wk -> v[b,h,:] (blocks 0..127) ========
    // block j: b = j>>6, h = (j>>2)&15, quarter = j&3 (256 columns).
    if (bid < 128) {
        int b = bid >> 6, h = (bid >> 2) & 15, qtr = bid & 3;
        if (t < HD) shq[t] = g_q[b * HH + h * HD + t];
        __syncthreads();
        int i = qtr * 256 + t;
        const float* wkb = Wk + (size_t)(h * HD) * HH;
        float acc = 0.f;
#pragma unroll 8
        for (int o = 0; o < HD; o++)
            acc += shq[o] * wkb[(size_t)o * HH + i];
        g_v[(size_t)(b * NH + h) * HH + i] = acc;
        __syncthreads();
    }
    gbar(&g_bar[1]);

    // ======== Phase 3: e = mask ? exp(0.125 * v.h1) : 0 ; atomic z (all blocks) ========
    // block: b = bid>>7; kc = (bid&127)>>1 -> 32 k's; hh = bid&1 -> 8 heads (32KB smem).
    {
        int b = bid >> 7, rem = bid & 127, kc = rem >> 1, hh = rem & 1;
        float4* vs4 = (float4*)sh;
        const float4* vb = (const float4*)(g_v + (size_t)(b * NH + hh * 8) * HH);
#pragma unroll
        for (int j = 0; j < 8; j++) vs4[t + j * 256] = vb[t + j * 256];
        __syncthreads();

        int k0 = kc * 32 + warp * 4;
        const float4* r0 = (const float4*)(h1 + (size_t)(b * SS + k0 + 0) * HH);
        const float4* r1 = (const float4*)(h1 + (size_t)(b * SS + k0 + 1) * HH);
        const float4* r2 = (const float4*)(h1 + (size_t)(b * SS + k0 + 2) * HH);
        const float4* r3 = (const float4*)(h1 + (size_t)(b * SS + k0 + 3) * HH);

        float acc[8][4];
#pragma unroll
        for (int h = 0; h < 8; h++)
#pragma unroll
            for (int j = 0; j < 4; j++) acc[h][j] = 0.f;

#pragma unroll 2
        for (int m = 0; m < HH / 128; m++) {
            int idx = lane + m * 32;
            float4 x0 = r0[idx], x1 = r1[idx], x2 = r2[idx], x3 = r3[idx];
#pragma unroll
            for (int h = 0; h < 8; h++) {
                float4 v = vs4[h * (HH / 4) + idx];
                acc[h][0] += v.x * x0.x + v.y * x0.y + v.z * x0.z + v.w * x0.w;
                acc[h][1] += v.x * x1.x + v.y * x1.y + v.z * x1.z + v.w * x1.w;
                acc[h][2] += v.x * x2.x + v.y * x2.y + v.z * x2.z + v.w * x2.w;
                acc[h][3] += v.x * x3.x + v.y * x3.y + v.z * x3.z + v.w * x3.w;
            }
        }
#pragma unroll
        for (int h = 0; h < 8; h++)
#pragma unroll
            for (int j = 0; j < 4; j++) {
                float s = acc[h][j];
#pragma unroll
                for (int off = 16; off; off >>= 1) s += __shfl_xor_sync(0xffffffffu, s, off);
                acc[h][j] = s;
            }
        {
            int h = lane & 7, j = lane >> 3;
            int k = k0 + j;
            float e = 0.f;
            if (mask_at(sm, b * SS + k, mode)) e = __expf(acc[h][j] * 0.125f);
            g_e[(size_t)(b * NH + hh * 8 + h) * SS + k] = e;
            atomicAdd(&g_z[b * NH + hh * 8 + h], e);
        }
        __syncthreads();
    }
    gbar(&g_bar[2]);

    // ======== Phase 4: column-tiled weights + streaming broadcast ========
    // block: b = bid>>7; cg = (bid>>5)&3 -> 512 cols; rg = bid&31 -> 64 rows.
    // Each block computes w for ONLY its 512 columns (16h x 512 e-reads = 32KB;
    // 8MB aggregate), then writes 64 rows x 512 cols via __stcs.
    {
        int b = bid >> 7, rem = bid & 127;
        int c0 = (rem >> 5) * 512;
        int r0 = (rem & 31) * 64;

        if (t < NH) ziv[t] = 1.f / (g_z[b * NH + t] * (float)NH);
        __syncthreads();

#pragma unroll
        for (int p = 0; p < 2; p++) {
            int c = c0 + t + p * 256;
            float wv = 0.f;
#pragma unroll
            for (int h = 0; h < NH; h++)
                wv += g_e[(size_t)(b * NH + h) * SS + c] * ziv[h];
            sh[t + p * 256] = wv;
        }
        __syncthreads();

        const float4* s4 = (const float4*)sh;   // 128 float4 = 512 cols
        float4 v0 = s4[lane], v1 = s4[lane + 32], v2 = s4[lane + 64], v3 = s4[lane + 96];
        int rowbase = r0 + warp * 8;
#pragma unroll
        for (int j = 0; j < 8; j++) {
            float4* dst = (float4*)(out + (size_t)(b * SS + rowbase + j) * SS + c0);
            __stcs(dst + lane,      v0);
            __stcs(dst + lane + 32, v1);
            __stcs(dst + lane + 64, v2);
            __stcs(dst + lane + 96, v3);
        }
    }
}

extern "C" void kernel_launch(void* const* d_in, const int* in_sizes, int n_in,
                              void* d_out, int out_size) {
    const float* h1 = (const float*)d_in[0];   // [B,S,H]
    const float* h2 = (const float*)d_in[1];   // [B,A,H]
    const void*  sm = d_in[2];                 // [B,S]
    const void*  am = d_in[3];                 // [B,A]
    const float* Wq = (const float*)d_in[4];   // [H,H]
    const float* Wk = (const float*)d_in[5];   // [H,H]
    float* out = (float*)d_out;                // [B,S,S]

    k_fused<<<NBLK, 256>>>(h1, h2, sm, am, Wq, Wk, out);
}